// round 14
// baseline (speedup 1.0000x reference)
#include <cuda_runtime.h>
#include <cuda_fp16.h>
#include <math.h>

// Problem constants (fixed by the reference)
#define NMAX 50000
#define EMAX 1600000
#define NEG_SLOPE 0.2f

#define SCAN_T 256
#define SCAN_I 8
#define SCAN_CHUNK (SCAN_T * SCAN_I)   // 2048 elements per block
#define SCAN_MAXB ((NMAX + SCAN_CHUNK - 1) / SCAN_CHUNK + 1)

// ---------------------------------------------------------------------------
// Scratch (static __device__ globals; runtime alloc is forbidden)
// ---------------------------------------------------------------------------
__device__ __half2 g_h1h[NMAX * 64];  // [N,128] layer-1 features, fp16
__device__ float4  g_out1[NMAX * 32]; // [N,128] layer-1 output (post ELU), fp32
__device__ float4  g_alS1[NMAX];      // [N,4] attention logits (src)
__device__ float4  g_alD1[NMAX];      // [N,4] attention logits (dst)

__device__ __half2 g_h2h[NMAX * 32];  // [N,64] layer-2 features, fp16
__device__ float   g_alS2[NMAX];
__device__ float   g_alD2[NMAX];

__device__ int     g_is64;            // edge_index dtype flag (1 = int64)
__device__ int     g_deg[NMAX];       // dst-degree histogram
__device__ int     g_row[NMAX + 1];   // CSR row offsets (by dst)
__device__ int     g_cursor[NMAX];    // scatter cursors
__device__ int     g_esrc[EMAX];      // src ids sorted by dst
__device__ int     g_bsum[SCAN_MAXB]; // per-block degree sums
__device__ int     g_boff[SCAN_MAXB]; // per-block exclusive offsets

// ---------------------------------------------------------------------------
// Helpers
// ---------------------------------------------------------------------------
__device__ __forceinline__ float lrelu(float x) {
    return x > 0.f ? x : NEG_SLOPE * x;
}
__device__ __forceinline__ float comp4(float4 v, int i) {
    return i == 0 ? v.x : (i == 1 ? v.y : (i == 2 ? v.z : v.w));
}
__device__ __forceinline__ unsigned f2tf32(float f) {
    unsigned u;
    asm("cvt.rna.tf32.f32 %0, %1;" : "=r"(u) : "f"(f));
    return u;
}
__device__ __forceinline__ void mma_tf32(float c[4],
                                         unsigned a0, unsigned a1,
                                         unsigned a2, unsigned a3,
                                         unsigned b0, unsigned b1) {
    asm volatile(
        "mma.sync.aligned.m16n8k8.row.col.f32.tf32.tf32.f32 "
        "{%0,%1,%2,%3}, {%4,%5,%6,%7}, {%8,%9}, {%0,%1,%2,%3};"
        : "+f"(c[0]), "+f"(c[1]), "+f"(c[2]), "+f"(c[3])
        : "r"(a0), "r"(a1), "r"(a2), "r"(a3), "r"(b0), "r"(b1));
}

// ---------------------------------------------------------------------------
// zero_deg + dtype probe fused (block 0 runs the 256-entry int64 probe).
// ---------------------------------------------------------------------------
__global__ void zero_probe_kernel(const void* ei, int n) {
    if (blockIdx.x == 0) {
        __shared__ int bad;
        if (threadIdx.x == 0) bad = 0;
        __syncthreads();
        const long long* p = (const long long*)ei;
        long long v = p[threadIdx.x];
        if (v < 0 || v >= n) atomicOr(&bad, 1);
        __syncthreads();
        if (threadIdx.x == 0) g_is64 = bad ? 0 : 1;
    }
    int i = blockIdx.x * blockDim.x + threadIdx.x;
    if (i < n) g_deg[i] = 0;
}

// ---------------------------------------------------------------------------
// CSR build: histogram -> 3-phase scan -> permute
// ---------------------------------------------------------------------------
__global__ void hist_kernel(const void* __restrict__ ei, int E, int n) {
    int e = blockIdx.x * blockDim.x + threadIdx.x;
    if (e >= E) return;
    int d;
    if (g_is64) d = (int)((const long long*)ei)[E + e];
    else        d = ((const int*)ei)[E + e];
    d = min(max(d, 0), n - 1);
    atomicAdd(&g_deg[d], 1);
}

// Phase A: per-block sum of 2048 degrees.
__global__ __launch_bounds__(SCAN_T) void scanA_kernel(int n) {
    __shared__ int sm[SCAN_T];
    int t = threadIdx.x;
    int base = blockIdx.x * SCAN_CHUNK + t * SCAN_I;
    int s = 0;
#pragma unroll
    for (int i = 0; i < SCAN_I; i++) {
        int idx = base + i;
        if (idx < n) s += g_deg[idx];
    }
    sm[t] = s;
    __syncthreads();
#pragma unroll
    for (int off = SCAN_T / 2; off > 0; off >>= 1) {
        if (t < off) sm[t] += sm[t + off];
        __syncthreads();
    }
    if (t == 0) g_bsum[blockIdx.x] = sm[0];
}

// Phase B: serial exclusive scan over <=25 block sums (tiny).
__global__ void scanB_kernel(int nb, int n) {
    if (threadIdx.x != 0) return;
    int acc = 0;
    for (int i = 0; i < nb; i++) {
        g_boff[i] = acc;
        acc += g_bsum[i];
    }
    g_row[n] = acc;
}

// Phase C: per-block exclusive scan with global offset; writes row + cursor.
__global__ __launch_bounds__(SCAN_T) void scanC_kernel(int n) {
    __shared__ int sm[SCAN_T];
    int t = threadIdx.x;
    int base = blockIdx.x * SCAN_CHUNK + t * SCAN_I;
    int loc[SCAN_I];
    int s = 0;
#pragma unroll
    for (int i = 0; i < SCAN_I; i++) {
        int idx = base + i;
        loc[i] = (idx < n) ? g_deg[idx] : 0;
        s += loc[i];
    }
    sm[t] = s;
    __syncthreads();
#pragma unroll
    for (int off = 1; off < SCAN_T; off <<= 1) {
        int v = (t >= off) ? sm[t - off] : 0;
        __syncthreads();
        sm[t] += v;
        __syncthreads();
    }
    int acc = ((t == 0) ? 0 : sm[t - 1]) + g_boff[blockIdx.x];
#pragma unroll
    for (int i = 0; i < SCAN_I; i++) {
        int idx = base + i;
        if (idx < n) {
            g_row[idx] = acc;
            g_cursor[idx] = acc;
            acc += loc[i];
        }
    }
}

__global__ void permute_kernel(const void* __restrict__ ei, int E, int n) {
    int e = blockIdx.x * blockDim.x + threadIdx.x;
    if (e >= E) return;
    int s, d;
    if (g_is64) {
        s = (int)((const long long*)ei)[e];
        d = (int)((const long long*)ei)[E + e];
    } else {
        s = ((const int*)ei)[e];
        d = ((const int*)ei)[E + e];
    }
    s = min(max(s, 0), n - 1);
    d = min(max(d, 0), n - 1);
    int pos = atomicAdd(&g_cursor[d], 1);
    if (pos < EMAX) g_esrc[pos] = s;
}

// ---------------------------------------------------------------------------
// TF32 tensor-core GEMM with fused attention-logit epilogue.
// H[M, NC] = X[M, 128] @ W[128, NC] via mma.sync m16n8k8 tf32.
// LAYER 1: NC=128, tile 64x128, warps 4(m) x 2(n).
// LAYER 2: NC=64,  tile 128x64, warps 8(m) x 1(n).
// ---------------------------------------------------------------------------
template <int LAYER>
__global__ __launch_bounds__(256) void gemm_mma_kernel(const float* __restrict__ Xin,
                                                       const float* __restrict__ W,
                                                       const float* __restrict__ aS,
                                                       const float* __restrict__ aD,
                                                       int M) {
    constexpr int NC = (LAYER == 1) ? 128 : 64;
    constexpr int MT = (LAYER == 1) ? 64 : 128;   // rows per block
    constexpr int WM = (LAYER == 1) ? 4 : 8;      // warps along M
    constexpr int XS = 36;                        // Xs row stride
    constexpr int WR = NC + 8;                    // Ws row stride
    const float* __restrict__ X = (LAYER == 1) ? Xin : (const float*)g_out1;
    __half2* __restrict__ Hh = (LAYER == 1) ? g_h1h : g_h2h;

    __shared__ unsigned Xs[MT][XS];   // tf32 bits
    __shared__ unsigned Ws[32][WR];   // tf32 bits

    const int t = threadIdx.x;
    const int w = t >> 5, lane = t & 31;
    const int g = lane >> 2, tig = lane & 3;
    const int wm = w % WM, wn = w / WM;
    const int nb = wn * 64;
    const int row0 = blockIdx.x * MT;

    float c[8][4];
#pragma unroll
    for (int i = 0; i < 8; i++)
#pragma unroll
        for (int j = 0; j < 4; j++) c[i][j] = 0.f;

    for (int kk = 0; kk < 128; kk += 32) {
#pragma unroll
        for (int i = 0; i < MT / 32; i++) {
            int idx = i * 256 + t;
            int r = idx >> 3, c4 = idx & 7;
            int gr = row0 + r;
            float4 v = make_float4(0.f, 0.f, 0.f, 0.f);
            if (gr < M) v = *(const float4*)&X[gr * 128 + kk + c4 * 4];
            unsigned* dst = &Xs[r][c4 * 4];
            dst[0] = f2tf32(v.x); dst[1] = f2tf32(v.y);
            dst[2] = f2tf32(v.z); dst[3] = f2tf32(v.w);
        }
#pragma unroll
        for (int i = 0; i < NC / 32; i++) {
            int idx = i * 256 + t;
            int r = idx / (NC / 4), c4 = idx % (NC / 4);
            float4 v = *(const float4*)&W[(kk + r) * NC + c4 * 4];
            unsigned* dst = &Ws[r][c4 * 4];
            dst[0] = f2tf32(v.x); dst[1] = f2tf32(v.y);
            dst[2] = f2tf32(v.z); dst[3] = f2tf32(v.w);
        }
        __syncthreads();

#pragma unroll
        for (int ks = 0; ks < 4; ks++) {
            int k0 = ks * 8;
            unsigned a0 = Xs[wm * 16 + g][k0 + tig];
            unsigned a1 = Xs[wm * 16 + g + 8][k0 + tig];
            unsigned a2 = Xs[wm * 16 + g][k0 + tig + 4];
            unsigned a3 = Xs[wm * 16 + g + 8][k0 + tig + 4];
#pragma unroll
            for (int nt = 0; nt < 8; nt++) {
                unsigned b0 = Ws[k0 + tig][nb + nt * 8 + g];
                unsigned b1 = Ws[k0 + tig + 4][nb + nt * 8 + g];
                mma_tf32(c[nt], a0, a1, a2, a3, b0, b1);
            }
        }
        __syncthreads();
    }

    const int r0g = row0 + wm * 16 + g;
    const int r1g = r0g + 8;

#pragma unroll
    for (int nt = 0; nt < 8; nt++) {
        int col = nb + nt * 8 + tig * 2;
        if (r0g < M)
            Hh[r0g * (NC / 2) + col / 2] = __floats2half2_rn(c[nt][0], c[nt][1]);
        if (r1g < M)
            Hh[r1g * (NC / 2) + col / 2] = __floats2half2_rn(c[nt][2], c[nt][3]);
    }

    if (LAYER == 1) {
        float sA0[2] = {0.f, 0.f}, sD0[2] = {0.f, 0.f};
        float sA1[2] = {0.f, 0.f}, sD1[2] = {0.f, 0.f};
#pragma unroll
        for (int nt = 0; nt < 8; nt++) {
            int col = nb + nt * 8 + tig * 2;
            int hl = nt >> 2;
            float av0 = aS[col], av1 = aS[col + 1];
            float dv0 = aD[col], dv1 = aD[col + 1];
            sA0[hl] += c[nt][0] * av0 + c[nt][1] * av1;
            sD0[hl] += c[nt][0] * dv0 + c[nt][1] * dv1;
            sA1[hl] += c[nt][2] * av0 + c[nt][3] * av1;
            sD1[hl] += c[nt][2] * dv0 + c[nt][3] * dv1;
        }
#pragma unroll
        for (int off = 1; off <= 2; off <<= 1) {
#pragma unroll
            for (int hl = 0; hl < 2; hl++) {
                sA0[hl] += __shfl_xor_sync(0xFFFFFFFF, sA0[hl], off);
                sD0[hl] += __shfl_xor_sync(0xFFFFFFFF, sD0[hl], off);
                sA1[hl] += __shfl_xor_sync(0xFFFFFFFF, sA1[hl], off);
                sD1[hl] += __shfl_xor_sync(0xFFFFFFFF, sD1[hl], off);
            }
        }
        if (tig == 0) {
            int hb = wn * 2;
            if (r0g < M) {
#pragma unroll
                for (int hl = 0; hl < 2; hl++) {
                    ((float*)g_alS1)[r0g * 4 + hb + hl] = sA0[hl];
                    ((float*)g_alD1)[r0g * 4 + hb + hl] = sD0[hl];
                }
            }
            if (r1g < M) {
#pragma unroll
                for (int hl = 0; hl < 2; hl++) {
                    ((float*)g_alS1)[r1g * 4 + hb + hl] = sA1[hl];
                    ((float*)g_alD1)[r1g * 4 + hb + hl] = sD1[hl];
                }
            }
        }
    } else {
        float sA0 = 0.f, sD0 = 0.f, sA1 = 0.f, sD1 = 0.f;
#pragma unroll
        for (int nt = 0; nt < 8; nt++) {
            int col = nt * 8 + tig * 2;
            float av0 = aS[col], av1 = aS[col + 1];
            float dv0 = aD[col], dv1 = aD[col + 1];
            sA0 += c[nt][0] * av0 + c[nt][1] * av1;
            sD0 += c[nt][0] * dv0 + c[nt][1] * dv1;
            sA1 += c[nt][2] * av0 + c[nt][3] * av1;
            sD1 += c[nt][2] * dv0 + c[nt][3] * dv1;
        }
#pragma unroll
        for (int off = 1; off <= 2; off <<= 1) {
            sA0 += __shfl_xor_sync(0xFFFFFFFF, sA0, off);
            sD0 += __shfl_xor_sync(0xFFFFFFFF, sD0, off);
            sA1 += __shfl_xor_sync(0xFFFFFFFF, sA1, off);
            sD1 += __shfl_xor_sync(0xFFFFFFFF, sD1, off);
        }
        if (tig == 0) {
            if (r0g < M) { g_alS2[r0g] = sA0; g_alD2[r0g] = sD0; }
            if (r1g < M) { g_alS2[r1g] = sA1; g_alD2[r1g] = sD1; }
        }
    }
}

// ---------------------------------------------------------------------------
// Fused GAT layer 1: warp per dst node, TWO edges per iteration.
// Half-warps (16 lanes) each own one edge of a pair; lane loads 16B (8 ch).
// Halves combined with shfl_xor(16) at the end. No atomics.
// ---------------------------------------------------------------------------
__global__ __launch_bounds__(256) void gat1_kernel(const float* __restrict__ b1,
                                                   int n) {
    __shared__ int ssrc[8][32];
    __shared__ float4 sev[8][32];

    int w = threadIdx.x >> 5;
    int lane = threadIdx.x & 31;
    int node = blockIdx.x * 8 + w;
    if (node >= n) return;
    int sl = lane & 15;        // sub-lane in half-warp: channels sl*8..sl*8+7
    int half = lane >> 4;      // which edge of the pair
    int headL = sl >> 2;       // head covering this lane's channels

    int r0 = g_row[node];
    int r1 = g_row[node + 1];
    float4 ad = g_alD1[node];

    float acc[8];
#pragma unroll
    for (int i = 0; i < 8; i++) acc[i] = 0.f;
    float4 den = make_float4(0.f, 0.f, 0.f, 0.f);

    for (int base = r0; base < r1; base += 32) {
        int e = base + lane;
        int s = 0;
        float4 ev = make_float4(0.f, 0.f, 0.f, 0.f);
        if (e < r1) {
            s = g_esrc[e];
            float4 as = g_alS1[s];
            ev.x = __expf(lrelu(as.x + ad.x));
            ev.y = __expf(lrelu(as.y + ad.y));
            ev.z = __expf(lrelu(as.z + ad.z));
            ev.w = __expf(lrelu(as.w + ad.w));
            den.x += ev.x; den.y += ev.y; den.z += ev.z; den.w += ev.w;
        }
        ssrc[w][lane] = s;
        sev[w][lane] = ev;
        __syncwarp();

        int cnt = min(32, r1 - base);
#pragma unroll 4
        for (int j = 0; j < cnt; j += 2) {
            int idx = j + half;
            bool valid = idx < cnt;
            int sj = ssrc[w][valid ? idx : j];
            float sc = valid ? ((const float*)(sev[w] + idx))[headL] : 0.f;
            uint4 raw = *reinterpret_cast<const uint4*>(&g_h1h[sj * 64 + sl * 4]);
            float2 v0 = __half22float2(*reinterpret_cast<__half2*>(&raw.x));
            float2 v1 = __half22float2(*reinterpret_cast<__half2*>(&raw.y));
            float2 v2 = __half22float2(*reinterpret_cast<__half2*>(&raw.z));
            float2 v3 = __half22float2(*reinterpret_cast<__half2*>(&raw.w));
            acc[0] += v0.x * sc; acc[1] += v0.y * sc;
            acc[2] += v1.x * sc; acc[3] += v1.y * sc;
            acc[4] += v2.x * sc; acc[5] += v2.y * sc;
            acc[6] += v3.x * sc; acc[7] += v3.y * sc;
        }
        __syncwarp();
    }

    // Combine the two half-warps (same channel mapping on both halves)
#pragma unroll
    for (int i = 0; i < 8; i++)
        acc[i] += __shfl_xor_sync(0xFFFFFFFF, acc[i], 16);

    // Reduce denominators across the warp (per-head sums)
#pragma unroll
    for (int off = 16; off > 0; off >>= 1) {
        den.x += __shfl_xor_sync(0xFFFFFFFF, den.x, off);
        den.y += __shfl_xor_sync(0xFFFFFFFF, den.y, off);
        den.z += __shfl_xor_sync(0xFFFFFFFF, den.z, off);
        den.w += __shfl_xor_sync(0xFFFFFFFF, den.w, off);
    }

    // Self-loop (both halves compute identically; only half 0 writes)
    float4 asn = g_alS1[node];
    float4 evs;
    evs.x = __expf(lrelu(asn.x + ad.x));
    evs.y = __expf(lrelu(asn.y + ad.y));
    evs.z = __expf(lrelu(asn.z + ad.z));
    evs.w = __expf(lrelu(asn.w + ad.w));
    float eh = comp4(evs, headL);
    {
        uint4 raw = *reinterpret_cast<const uint4*>(&g_h1h[node * 64 + sl * 4]);
        float2 v0 = __half22float2(*reinterpret_cast<__half2*>(&raw.x));
        float2 v1 = __half22float2(*reinterpret_cast<__half2*>(&raw.y));
        float2 v2 = __half22float2(*reinterpret_cast<__half2*>(&raw.z));
        float2 v3 = __half22float2(*reinterpret_cast<__half2*>(&raw.w));
        acc[0] += eh * v0.x; acc[1] += eh * v0.y;
        acc[2] += eh * v1.x; acc[3] += eh * v1.y;
        acc[4] += eh * v2.x; acc[5] += eh * v2.y;
        acc[6] += eh * v3.x; acc[7] += eh * v3.y;
    }

    float inv = 1.f / (comp4(den, headL) + eh + 1e-16f);
    if (half == 0) {
        float4 ba = ((const float4*)b1)[sl * 2];
        float4 bb = ((const float4*)b1)[sl * 2 + 1];
        float4 o0, o1;
        o0.x = acc[0] * inv + ba.x;
        o0.y = acc[1] * inv + ba.y;
        o0.z = acc[2] * inv + ba.z;
        o0.w = acc[3] * inv + ba.w;
        o1.x = acc[4] * inv + bb.x;
        o1.y = acc[5] * inv + bb.y;
        o1.z = acc[6] * inv + bb.z;
        o1.w = acc[7] * inv + bb.w;
        // ELU
        o0.x = o0.x > 0.f ? o0.x : expm1f(o0.x);
        o0.y = o0.y > 0.f ? o0.y : expm1f(o0.y);
        o0.z = o0.z > 0.f ? o0.z : expm1f(o0.z);
        o0.w = o0.w > 0.f ? o0.w : expm1f(o0.w);
        o1.x = o1.x > 0.f ? o1.x : expm1f(o1.x);
        o1.y = o1.y > 0.f ? o1.y : expm1f(o1.y);
        o1.z = o1.z > 0.f ? o1.z : expm1f(o1.z);
        o1.w = o1.w > 0.f ? o1.w : expm1f(o1.w);
        g_out1[node * 32 + sl * 2] = o0;
        g_out1[node * 32 + sl * 2 + 1] = o1;
    }
}

// ---------------------------------------------------------------------------
// Fused GAT layer 2: warp per dst node, TWO edges per iteration.
// Half-warps each own one edge; lane loads 8B (4 ch). Writes d_out fp32.
// ---------------------------------------------------------------------------
__global__ __launch_bounds__(256) void gat2_kernel(const float* __restrict__ b2,
                                                   float* __restrict__ out,
                                                   int n) {
    __shared__ int ssrc[8][32];
    __shared__ float sev[8][32];

    int w = threadIdx.x >> 5;
    int lane = threadIdx.x & 31;
    int node = blockIdx.x * 8 + w;
    if (node >= n) return;
    int sl = lane & 15;        // channels sl*4..sl*4+3
    int half = lane >> 4;

    int r0 = g_row[node];
    int r1 = g_row[node + 1];
    float ad = g_alD2[node];

    float acc[4];
#pragma unroll
    for (int i = 0; i < 4; i++) acc[i] = 0.f;
    float den = 0.f;

    for (int base = r0; base < r1; base += 32) {
        int e = base + lane;
        int s = 0;
        float ev = 0.f;
        if (e < r1) {
            s = g_esrc[e];
            ev = __expf(lrelu(g_alS2[s] + ad));
            den += ev;
        }
        ssrc[w][lane] = s;
        sev[w][lane] = ev;
        __syncwarp();

        int cnt = min(32, r1 - base);
#pragma unroll 4
        for (int j = 0; j < cnt; j += 2) {
            int idx = j + half;
            bool valid = idx < cnt;
            int sj = ssrc[w][valid ? idx : j];
            float sc = valid ? sev[w][idx] : 0.f;
            uint2 raw = *reinterpret_cast<const uint2*>(&g_h2h[sj * 32 + sl * 2]);
            float2 v0 = __half22float2(*reinterpret_cast<__half2*>(&raw.x));
            float2 v1 = __half22float2(*reinterpret_cast<__half2*>(&raw.y));
            acc[0] += v0.x * sc; acc[1] += v0.y * sc;
            acc[2] += v1.x * sc; acc[3] += v1.y * sc;
        }
        __syncwarp();
    }

#pragma unroll
    for (int i = 0; i < 4; i++)
        acc[i] += __shfl_xor_sync(0xFFFFFFFF, acc[i], 16);

#pragma unroll
    for (int off = 16; off > 0; off >>= 1)
        den += __shfl_xor_sync(0xFFFFFFFF, den, off);

    // Self-loop
    float eh = __expf(lrelu(g_alS2[node] + ad));
    {
        uint2 raw = *reinterpret_cast<const uint2*>(&g_h2h[node * 32 + sl * 2]);
        float2 v0 = __half22float2(*reinterpret_cast<__half2*>(&raw.x));
        float2 v1 = __half22float2(*reinterpret_cast<__half2*>(&raw.y));
        acc[0] += eh * v0.x; acc[1] += eh * v0.y;
        acc[2] += eh * v1.x; acc[3] += eh * v1.y;
    }

    float inv = 1.f / (den + eh + 1e-16f);
    if (half == 0) {
        float4 bv = ((const float4*)b2)[sl];
        float4 o;
        o.x = acc[0] * inv + bv.x;
        o.y = acc[1] * inv + bv.y;
        o.z = acc[2] * inv + bv.z;
        o.w = acc[3] * inv + bv.w;
        ((float4*)out)[node * 16 + sl] = o;
    }
}

// ---------------------------------------------------------------------------
// Launch: CSR build forked onto a side stream, overlapped with gemm1.
// ---------------------------------------------------------------------------
extern "C" void kernel_launch(void* const* d_in, const int* in_sizes, int n_in,
                              void* d_out, int out_size) {
    const float* x   = (const float*)d_in[0];
    const void*  ei  = d_in[1];
    const float* W1  = (const float*)d_in[2];
    const float* aS1 = (const float*)d_in[3];
    const float* aD1 = (const float*)d_in[4];
    const float* b1  = (const float*)d_in[5];
    const float* W2  = (const float*)d_in[6];
    const float* aS2 = (const float*)d_in[7];
    const float* aD2 = (const float*)d_in[8];
    const float* b2  = (const float*)d_in[9];
    float* out       = (float*)d_out;

    const int n = in_sizes[0] / 128;
    const int E = in_sizes[1] / 2;

    const int gemm1_blocks = (n + 63) / 64;
    const int gemm2_blocks = (n + 127) / 128;
    const int node_blocks = (n + 7) / 8;        // warp per node
    const int edge_blocks = (E + 255) / 256;
    const int scan_blocks = (n + SCAN_CHUNK - 1) / SCAN_CHUNK;

    cudaStream_t side = nullptr;
    cudaEvent_t evF = nullptr, evJ = nullptr;
    bool fork = (cudaStreamCreateWithFlags(&side, cudaStreamNonBlocking) == cudaSuccess);
    if (fork) fork = (cudaEventCreateWithFlags(&evF, cudaEventDisableTiming) == cudaSuccess);
    if (fork) fork = (cudaEventCreateWithFlags(&evJ, cudaEventDisableTiming) == cudaSuccess);

    if (fork) {
        cudaEventRecord(evF, 0);
        cudaStreamWaitEvent(side, evF, 0);
        zero_probe_kernel<<<(n + 255) / 256, 256, 0, side>>>(ei, n);
        hist_kernel<<<edge_blocks, 256, 0, side>>>(ei, E, n);
        scanA_kernel<<<scan_blocks, SCAN_T, 0, side>>>(n);
        scanB_kernel<<<1, 32, 0, side>>>(scan_blocks, n);
        scanC_kernel<<<scan_blocks, SCAN_T, 0, side>>>(n);
        permute_kernel<<<edge_blocks, 256, 0, side>>>(ei, E, n);
        cudaEventRecord(evJ, side);

        gemm_mma_kernel<1><<<gemm1_blocks, 256>>>(x, W1, aS1, aD1, n);

        cudaStreamWaitEvent(0, evJ, 0);
    } else {
        zero_probe_kernel<<<(n + 255) / 256, 256>>>(ei, n);
        hist_kernel<<<edge_blocks, 256>>>(ei, E, n);
        scanA_kernel<<<scan_blocks, SCAN_T>>>(n);
        scanB_kernel<<<1, 32>>>(scan_blocks, n);
        scanC_kernel<<<scan_blocks, SCAN_T>>>(n);
        permute_kernel<<<edge_blocks, 256>>>(ei, E, n);
        gemm_mma_kernel<1><<<gemm1_blocks, 256>>>(x, W1, aS1, aD1, n);
    }

    gat1_kernel<<<node_blocks, 256>>>(b1, n);
    gemm_mma_kernel<2><<<gemm2_blocks, 256>>>(nullptr, W2, aS2, aD2, n);
    gat2_kernel<<<node_blocks, 256>>>(b2, out, n);

    if (evF) cudaEventDestroy(evF);
    if (evJ) cudaEventDestroy(evJ);
    if (side) cudaStreamDestroy(side);
}

// round 15
// speedup vs baseline: 1.0572x; 1.0572x over previous
#include <cuda_runtime.h>
#include <cuda_fp16.h>
#include <math.h>

// Problem constants (fixed by the reference)
#define NMAX 50000
#define EMAX 1600000
#define NEG_SLOPE 0.2f

#define SCAN_T 256
#define SCAN_I 8
#define SCAN_CHUNK (SCAN_T * SCAN_I)   // 2048 elements per block
#define SCAN_MAXB ((NMAX + SCAN_CHUNK - 1) / SCAN_CHUNK + 1)

// ---------------------------------------------------------------------------
// Scratch (static __device__ globals; runtime alloc is forbidden)
// ---------------------------------------------------------------------------
__device__ __half2 g_h1h[NMAX * 64];  // [N,128] layer-1 features, fp16
__device__ float4  g_out1[NMAX * 32]; // [N,128] layer-1 output (post ELU), fp32
__device__ float4  g_alS1[NMAX];      // [N,4] attention logits (src)
__device__ float4  g_alD1[NMAX];      // [N,4] attention logits (dst)

__device__ __half2 g_h2h[NMAX * 32];  // [N,64] layer-2 features, fp16
__device__ float   g_alS2[NMAX];
__device__ float   g_alD2[NMAX];

__device__ int     g_is64;            // edge_index dtype flag (1 = int64)
__device__ int     g_deg[NMAX];       // dst-degree histogram
__device__ int     g_row[NMAX + 1];   // CSR row offsets (by dst)
__device__ int     g_cursor[NMAX];    // scatter cursors
__device__ int     g_esrc[EMAX];      // src ids sorted by dst
__device__ unsigned long long g_state[SCAN_MAXB];  // lookback: (flag<<32)|value

// ---------------------------------------------------------------------------
// Helpers
// ---------------------------------------------------------------------------
__device__ __forceinline__ float lrelu(float x) {
    return x > 0.f ? x : NEG_SLOPE * x;
}
__device__ __forceinline__ float comp4(float4 v, int i) {
    return i == 0 ? v.x : (i == 1 ? v.y : (i == 2 ? v.z : v.w));
}
__device__ __forceinline__ unsigned f2tf32(float f) {
    unsigned u;
    asm("cvt.rna.tf32.f32 %0, %1;" : "=r"(u) : "f"(f));
    return u;
}
__device__ __forceinline__ void mma_tf32(float c[4],
                                         unsigned a0, unsigned a1,
                                         unsigned a2, unsigned a3,
                                         unsigned b0, unsigned b1) {
    asm volatile(
        "mma.sync.aligned.m16n8k8.row.col.f32.tf32.tf32.f32 "
        "{%0,%1,%2,%3}, {%4,%5,%6,%7}, {%8,%9}, {%0,%1,%2,%3};"
        : "+f"(c[0]), "+f"(c[1]), "+f"(c[2]), "+f"(c[3])
        : "r"(a0), "r"(a1), "r"(a2), "r"(a3), "r"(b0), "r"(b1));
}

// ---------------------------------------------------------------------------
// zero_deg + dtype probe + scan-state reset, fused.
// ---------------------------------------------------------------------------
__global__ void zero_probe_kernel(const void* ei, int n) {
    if (blockIdx.x == 0) {
        __shared__ int bad;
        if (threadIdx.x == 0) bad = 0;
        __syncthreads();
        const long long* p = (const long long*)ei;
        long long v = p[threadIdx.x];
        if (v < 0 || v >= n) atomicOr(&bad, 1);
        __syncthreads();
        if (threadIdx.x == 0) g_is64 = bad ? 0 : 1;
    }
    int i = blockIdx.x * blockDim.x + threadIdx.x;
    if (i < n) g_deg[i] = 0;
    if (i < SCAN_MAXB) g_state[i] = 0ULL;
}

// ---------------------------------------------------------------------------
// CSR build: histogram -> single-kernel lookback scan -> permute
// ---------------------------------------------------------------------------
__global__ void hist_kernel(const void* __restrict__ ei, int E, int n) {
    int e = blockIdx.x * blockDim.x + threadIdx.x;
    if (e >= E) return;
    int d;
    if (g_is64) d = (int)((const long long*)ei)[E + e];
    else        d = ((const int*)ei)[E + e];
    d = min(max(d, 0), n - 1);
    atomicAdd(&g_deg[d], 1);
}

// Single-kernel exclusive scan with decoupled lookback.
// 25 blocks (all co-resident on 148 SMs -> spin is deadlock-free).
__global__ __launch_bounds__(SCAN_T) void scan_fused_kernel(int n) {
    __shared__ int sm[SCAN_T];
    __shared__ int sprefix;
    int t = threadIdx.x;
    int bid = blockIdx.x;
    int base = bid * SCAN_CHUNK + t * SCAN_I;
    int loc[SCAN_I];
    int s = 0;
#pragma unroll
    for (int i = 0; i < SCAN_I; i++) {
        int idx = base + i;
        loc[i] = (idx < n) ? g_deg[idx] : 0;
        s += loc[i];
    }
    sm[t] = s;
    __syncthreads();
    // inclusive Hillis-Steele over thread totals
#pragma unroll
    for (int off = 1; off < SCAN_T; off <<= 1) {
        int v = (t >= off) ? sm[t - off] : 0;
        __syncthreads();
        sm[t] += v;
        __syncthreads();
    }
    int total = sm[SCAN_T - 1];

    if (t == 0) {
        // publish aggregate (flag 1)
        atomicExch(&g_state[bid], (1ULL << 32) | (unsigned)total);
        // lookback over predecessors
        int run = 0;
        for (int i = bid - 1; i >= 0; i--) {
            unsigned long long st;
            do { st = atomicAdd(&g_state[i], 0ULL); } while ((st >> 32) == 0ULL);
            run += (int)(st & 0xFFFFFFFFULL);
            if ((st >> 32) == 2ULL) break;
        }
        // publish inclusive prefix (flag 2)
        atomicExch(&g_state[bid], (2ULL << 32) | (unsigned)(run + total));
        sprefix = run;
    }
    __syncthreads();

    int acc = ((t == 0) ? 0 : sm[t - 1]) + sprefix;
#pragma unroll
    for (int i = 0; i < SCAN_I; i++) {
        int idx = base + i;
        if (idx < n) {
            g_row[idx] = acc;
            g_cursor[idx] = acc;
            acc += loc[i];
        }
    }
    if (bid == gridDim.x - 1 && t == SCAN_T - 1) g_row[n] = sprefix + total;
}

__global__ void permute_kernel(const void* __restrict__ ei, int E, int n) {
    int e = blockIdx.x * blockDim.x + threadIdx.x;
    if (e >= E) return;
    int s, d;
    if (g_is64) {
        s = (int)((const long long*)ei)[e];
        d = (int)((const long long*)ei)[E + e];
    } else {
        s = ((const int*)ei)[e];
        d = ((const int*)ei)[E + e];
    }
    s = min(max(s, 0), n - 1);
    d = min(max(d, 0), n - 1);
    int pos = atomicAdd(&g_cursor[d], 1);
    if (pos < EMAX) g_esrc[pos] = s;
}

// ---------------------------------------------------------------------------
// TF32 tensor-core GEMM with fused attention-logit epilogue.
// H[M, NC] = X[M, 128] @ W[128, NC] via mma.sync m16n8k8 tf32.
// LAYER 1: NC=128, tile 64x128, warps 4(m) x 2(n).
// LAYER 2: NC=64,  tile 128x64, warps 8(m) x 1(n).
// ---------------------------------------------------------------------------
template <int LAYER>
__global__ __launch_bounds__(256) void gemm_mma_kernel(const float* __restrict__ Xin,
                                                       const float* __restrict__ W,
                                                       const float* __restrict__ aS,
                                                       const float* __restrict__ aD,
                                                       int M) {
    constexpr int NC = (LAYER == 1) ? 128 : 64;
    constexpr int MT = (LAYER == 1) ? 64 : 128;   // rows per block
    constexpr int WM = (LAYER == 1) ? 4 : 8;      // warps along M
    constexpr int XS = 36;                        // Xs row stride
    constexpr int WR = NC + 8;                    // Ws row stride
    const float* __restrict__ X = (LAYER == 1) ? Xin : (const float*)g_out1;
    __half2* __restrict__ Hh = (LAYER == 1) ? g_h1h : g_h2h;

    __shared__ unsigned Xs[MT][XS];   // tf32 bits
    __shared__ unsigned Ws[32][WR];   // tf32 bits

    const int t = threadIdx.x;
    const int w = t >> 5, lane = t & 31;
    const int g = lane >> 2, tig = lane & 3;
    const int wm = w % WM, wn = w / WM;
    const int nb = wn * 64;
    const int row0 = blockIdx.x * MT;

    float c[8][4];
#pragma unroll
    for (int i = 0; i < 8; i++)
#pragma unroll
        for (int j = 0; j < 4; j++) c[i][j] = 0.f;

    for (int kk = 0; kk < 128; kk += 32) {
#pragma unroll
        for (int i = 0; i < MT / 32; i++) {
            int idx = i * 256 + t;
            int r = idx >> 3, c4 = idx & 7;
            int gr = row0 + r;
            float4 v = make_float4(0.f, 0.f, 0.f, 0.f);
            if (gr < M) v = *(const float4*)&X[gr * 128 + kk + c4 * 4];
            unsigned* dst = &Xs[r][c4 * 4];
            dst[0] = f2tf32(v.x); dst[1] = f2tf32(v.y);
            dst[2] = f2tf32(v.z); dst[3] = f2tf32(v.w);
        }
#pragma unroll
        for (int i = 0; i < NC / 32; i++) {
            int idx = i * 256 + t;
            int r = idx / (NC / 4), c4 = idx % (NC / 4);
            float4 v = *(const float4*)&W[(kk + r) * NC + c4 * 4];
            unsigned* dst = &Ws[r][c4 * 4];
            dst[0] = f2tf32(v.x); dst[1] = f2tf32(v.y);
            dst[2] = f2tf32(v.z); dst[3] = f2tf32(v.w);
        }
        __syncthreads();

#pragma unroll
        for (int ks = 0; ks < 4; ks++) {
            int k0 = ks * 8;
            unsigned a0 = Xs[wm * 16 + g][k0 + tig];
            unsigned a1 = Xs[wm * 16 + g + 8][k0 + tig];
            unsigned a2 = Xs[wm * 16 + g][k0 + tig + 4];
            unsigned a3 = Xs[wm * 16 + g + 8][k0 + tig + 4];
#pragma unroll
            for (int nt = 0; nt < 8; nt++) {
                unsigned b0 = Ws[k0 + tig][nb + nt * 8 + g];
                unsigned b1 = Ws[k0 + tig + 4][nb + nt * 8 + g];
                mma_tf32(c[nt], a0, a1, a2, a3, b0, b1);
            }
        }
        __syncthreads();
    }

    const int r0g = row0 + wm * 16 + g;
    const int r1g = r0g + 8;

#pragma unroll
    for (int nt = 0; nt < 8; nt++) {
        int col = nb + nt * 8 + tig * 2;
        if (r0g < M)
            Hh[r0g * (NC / 2) + col / 2] = __floats2half2_rn(c[nt][0], c[nt][1]);
        if (r1g < M)
            Hh[r1g * (NC / 2) + col / 2] = __floats2half2_rn(c[nt][2], c[nt][3]);
    }

    if (LAYER == 1) {
        float sA0[2] = {0.f, 0.f}, sD0[2] = {0.f, 0.f};
        float sA1[2] = {0.f, 0.f}, sD1[2] = {0.f, 0.f};
#pragma unroll
        for (int nt = 0; nt < 8; nt++) {
            int col = nb + nt * 8 + tig * 2;
            int hl = nt >> 2;
            float av0 = aS[col], av1 = aS[col + 1];
            float dv0 = aD[col], dv1 = aD[col + 1];
            sA0[hl] += c[nt][0] * av0 + c[nt][1] * av1;
            sD0[hl] += c[nt][0] * dv0 + c[nt][1] * dv1;
            sA1[hl] += c[nt][2] * av0 + c[nt][3] * av1;
            sD1[hl] += c[nt][2] * dv0 + c[nt][3] * dv1;
        }
#pragma unroll
        for (int off = 1; off <= 2; off <<= 1) {
#pragma unroll
            for (int hl = 0; hl < 2; hl++) {
                sA0[hl] += __shfl_xor_sync(0xFFFFFFFF, sA0[hl], off);
                sD0[hl] += __shfl_xor_sync(0xFFFFFFFF, sD0[hl], off);
                sA1[hl] += __shfl_xor_sync(0xFFFFFFFF, sA1[hl], off);
                sD1[hl] += __shfl_xor_sync(0xFFFFFFFF, sD1[hl], off);
            }
        }
        if (tig == 0) {
            int hb = wn * 2;
            if (r0g < M) {
#pragma unroll
                for (int hl = 0; hl < 2; hl++) {
                    ((float*)g_alS1)[r0g * 4 + hb + hl] = sA0[hl];
                    ((float*)g_alD1)[r0g * 4 + hb + hl] = sD0[hl];
                }
            }
            if (r1g < M) {
#pragma unroll
                for (int hl = 0; hl < 2; hl++) {
                    ((float*)g_alS1)[r1g * 4 + hb + hl] = sA1[hl];
                    ((float*)g_alD1)[r1g * 4 + hb + hl] = sD1[hl];
                }
            }
        }
    } else {
        float sA0 = 0.f, sD0 = 0.f, sA1 = 0.f, sD1 = 0.f;
#pragma unroll
        for (int nt = 0; nt < 8; nt++) {
            int col = nt * 8 + tig * 2;
            float av0 = aS[col], av1 = aS[col + 1];
            float dv0 = aD[col], dv1 = aD[col + 1];
            sA0 += c[nt][0] * av0 + c[nt][1] * av1;
            sD0 += c[nt][0] * dv0 + c[nt][1] * dv1;
            sA1 += c[nt][2] * av0 + c[nt][3] * av1;
            sD1 += c[nt][2] * dv0 + c[nt][3] * dv1;
        }
#pragma unroll
        for (int off = 1; off <= 2; off <<= 1) {
            sA0 += __shfl_xor_sync(0xFFFFFFFF, sA0, off);
            sD0 += __shfl_xor_sync(0xFFFFFFFF, sD0, off);
            sA1 += __shfl_xor_sync(0xFFFFFFFF, sA1, off);
            sD1 += __shfl_xor_sync(0xFFFFFFFF, sD1, off);
        }
        if (tig == 0) {
            if (r0g < M) { g_alS2[r0g] = sA0; g_alD2[r0g] = sD0; }
            if (r1g < M) { g_alS2[r1g] = sA1; g_alD2[r1g] = sD1; }
        }
    }
}

// ---------------------------------------------------------------------------
// Fused GAT layer 1 (round-13 proven version): warp per dst node, 8B/lane
// fp16 gather, register accumulation, self-loop folded, ELU. No atomics.
// ---------------------------------------------------------------------------
__global__ __launch_bounds__(256) void gat1_kernel(const float* __restrict__ b1,
                                                   int n) {
    __shared__ int ssrc[8][32];
    __shared__ float4 sev[8][32];

    int w = threadIdx.x >> 5;
    int lane = threadIdx.x & 31;
    int node = blockIdx.x * 8 + w;
    if (node >= n) return;
    int head = lane >> 3;

    int r0 = g_row[node];
    int r1 = g_row[node + 1];
    float4 ad = g_alD1[node];

    float4 accv = make_float4(0.f, 0.f, 0.f, 0.f);
    float4 den = make_float4(0.f, 0.f, 0.f, 0.f);

    for (int base = r0; base < r1; base += 32) {
        int e = base + lane;
        int s = 0;
        float4 ev = make_float4(0.f, 0.f, 0.f, 0.f);
        if (e < r1) {
            s = g_esrc[e];
            float4 as = g_alS1[s];
            ev.x = __expf(lrelu(as.x + ad.x));
            ev.y = __expf(lrelu(as.y + ad.y));
            ev.z = __expf(lrelu(as.z + ad.z));
            ev.w = __expf(lrelu(as.w + ad.w));
            den.x += ev.x; den.y += ev.y; den.z += ev.z; den.w += ev.w;
        }
        ssrc[w][lane] = s;
        sev[w][lane] = ev;
        __syncwarp();

        int cnt = min(32, r1 - base);
#pragma unroll 4
        for (int j = 0; j < cnt; j++) {
            int sj = ssrc[w][j];                           // smem broadcast
            float sc = ((const float*)(sev[w] + j))[head]; // conflict-free
            uint2 raw = *reinterpret_cast<const uint2*>(&g_h1h[sj * 64 + lane * 2]);
            float2 va = __half22float2(*reinterpret_cast<__half2*>(&raw.x));
            float2 vb = __half22float2(*reinterpret_cast<__half2*>(&raw.y));
            accv.x += va.x * sc;
            accv.y += va.y * sc;
            accv.z += vb.x * sc;
            accv.w += vb.y * sc;
        }
        __syncwarp();
    }

#pragma unroll
    for (int off = 16; off > 0; off >>= 1) {
        den.x += __shfl_xor_sync(0xFFFFFFFF, den.x, off);
        den.y += __shfl_xor_sync(0xFFFFFFFF, den.y, off);
        den.z += __shfl_xor_sync(0xFFFFFFFF, den.z, off);
        den.w += __shfl_xor_sync(0xFFFFFFFF, den.w, off);
    }

    float4 asn = g_alS1[node];
    float4 evs;
    evs.x = __expf(lrelu(asn.x + ad.x));
    evs.y = __expf(lrelu(asn.y + ad.y));
    evs.z = __expf(lrelu(asn.z + ad.z));
    evs.w = __expf(lrelu(asn.w + ad.w));
    float eh = comp4(evs, head);
    {
        uint2 raw = *reinterpret_cast<const uint2*>(&g_h1h[node * 64 + lane * 2]);
        float2 va = __half22float2(*reinterpret_cast<__half2*>(&raw.x));
        float2 vb = __half22float2(*reinterpret_cast<__half2*>(&raw.y));
        accv.x += eh * va.x;
        accv.y += eh * va.y;
        accv.z += eh * vb.x;
        accv.w += eh * vb.y;
    }

    float inv = 1.f / (comp4(den, head) + eh + 1e-16f);
    float4 bv = ((const float4*)b1)[lane];
    float4 o;
    o.x = accv.x * inv + bv.x;
    o.y = accv.y * inv + bv.y;
    o.z = accv.z * inv + bv.z;
    o.w = accv.w * inv + bv.w;
    o.x = o.x > 0.f ? o.x : expm1f(o.x);
    o.y = o.y > 0.f ? o.y : expm1f(o.y);
    o.z = o.z > 0.f ? o.z : expm1f(o.z);
    o.w = o.w > 0.f ? o.w : expm1f(o.w);
    g_out1[node * 32 + lane] = o;
}

// ---------------------------------------------------------------------------
// Fused GAT layer 2 (round-13 proven version): warp per dst node, 1 head,
// 64 ch fp16. Writes d_out fp32.
// ---------------------------------------------------------------------------
__global__ __launch_bounds__(256) void gat2_kernel(const float* __restrict__ b2,
                                                   float* __restrict__ out,
                                                   int n) {
    __shared__ int ssrc[8][32];
    __shared__ float sev[8][32];

    int w = threadIdx.x >> 5;
    int lane = threadIdx.x & 31;
    int node = blockIdx.x * 8 + w;
    if (node >= n) return;

    int r0 = g_row[node];
    int r1 = g_row[node + 1];
    float ad = g_alD2[node];

    float2 accv = make_float2(0.f, 0.f);
    float den = 0.f;

    for (int base = r0; base < r1; base += 32) {
        int e = base + lane;
        int s = 0;
        float ev = 0.f;
        if (e < r1) {
            s = g_esrc[e];
            ev = __expf(lrelu(g_alS2[s] + ad));
            den += ev;
        }
        ssrc[w][lane] = s;
        sev[w][lane] = ev;
        __syncwarp();

        int cnt = min(32, r1 - base);
#pragma unroll 4
        for (int j = 0; j < cnt; j++) {
            int sj = ssrc[w][j];
            float ee = sev[w][j];
            float2 v = __half22float2(g_h2h[sj * 32 + lane]);
            accv.x += v.x * ee;
            accv.y += v.y * ee;
        }
        __syncwarp();
    }

#pragma unroll
    for (int off = 16; off > 0; off >>= 1)
        den += __shfl_xor_sync(0xFFFFFFFF, den, off);

    float eh = __expf(lrelu(g_alS2[node] + ad));
    float2 hv = __half22float2(g_h2h[node * 32 + lane]);
    accv.x += eh * hv.x;
    accv.y += eh * hv.y;

    float inv = 1.f / (den + eh + 1e-16f);
    float2 bv = ((const float2*)b2)[lane];
    float2 o;
    o.x = accv.x * inv + bv.x;
    o.y = accv.y * inv + bv.y;
    ((float2*)out)[node * 32 + lane] = o;
}

// ---------------------------------------------------------------------------
// Launch: CSR build forked onto a side stream, overlapped with gemm1.
// ---------------------------------------------------------------------------
extern "C" void kernel_launch(void* const* d_in, const int* in_sizes, int n_in,
                              void* d_out, int out_size) {
    const float* x   = (const float*)d_in[0];
    const void*  ei  = d_in[1];
    const float* W1  = (const float*)d_in[2];
    const float* aS1 = (const float*)d_in[3];
    const float* aD1 = (const float*)d_in[4];
    const float* b1  = (const float*)d_in[5];
    const float* W2  = (const float*)d_in[6];
    const float* aS2 = (const float*)d_in[7];
    const float* aD2 = (const float*)d_in[8];
    const float* b2  = (const float*)d_in[9];
    float* out       = (float*)d_out;

    const int n = in_sizes[0] / 128;
    const int E = in_sizes[1] / 2;

    const int gemm1_blocks = (n + 63) / 64;
    const int gemm2_blocks = (n + 127) / 128;
    const int node_blocks = (n + 7) / 8;        // warp per node
    const int edge_blocks = (E + 255) / 256;
    const int scan_blocks = (n + SCAN_CHUNK - 1) / SCAN_CHUNK;

    cudaStream_t side = nullptr;
    cudaEvent_t evF = nullptr, evJ = nullptr;
    bool fork = (cudaStreamCreateWithFlags(&side, cudaStreamNonBlocking) == cudaSuccess);
    if (fork) fork = (cudaEventCreateWithFlags(&evF, cudaEventDisableTiming) == cudaSuccess);
    if (fork) fork = (cudaEventCreateWithFlags(&evJ, cudaEventDisableTiming) == cudaSuccess);

    if (fork) {
        cudaEventRecord(evF, 0);
        cudaStreamWaitEvent(side, evF, 0);
        zero_probe_kernel<<<(n + 255) / 256, 256, 0, side>>>(ei, n);
        hist_kernel<<<edge_blocks, 256, 0, side>>>(ei, E, n);
        scan_fused_kernel<<<scan_blocks, SCAN_T, 0, side>>>(n);
        permute_kernel<<<edge_blocks, 256, 0, side>>>(ei, E, n);
        cudaEventRecord(evJ, side);

        gemm_mma_kernel<1><<<gemm1_blocks, 256>>>(x, W1, aS1, aD1, n);

        cudaStreamWaitEvent(0, evJ, 0);
    } else {
        zero_probe_kernel<<<(n + 255) / 256, 256>>>(ei, n);
        hist_kernel<<<edge_blocks, 256>>>(ei, E, n);
        scan_fused_kernel<<<scan_blocks, SCAN_T>>>(n);
        permute_kernel<<<edge_blocks, 256>>>(ei, E, n);
        gemm_mma_kernel<1><<<gemm1_blocks, 256>>>(x, W1, aS1, aD1, n);
    }

    gat1_kernel<<<node_blocks, 256>>>(b1, n);
    gemm_mma_kernel<2><<<gemm2_blocks, 256>>>(nullptr, W2, aS2, aD2, n);
    gat2_kernel<<<node_blocks, 256>>>(b2, out, n);

    if (evF) cudaEventDestroy(evF);
    if (evJ) cudaEventDestroy(evJ);
    if (side) cudaStreamDestroy(side);
}

// round 16
// speedup vs baseline: 1.0783x; 1.0199x over previous
#include <cuda_runtime.h>
#include <cuda_fp16.h>
#include <math.h>

// Problem constants (fixed by the reference)
#define NMAX 50000
#define EMAX 1600000
#define NEG_SLOPE 0.2f

#define SCAN_T 256
#define SCAN_I 8
#define SCAN_CHUNK (SCAN_T * SCAN_I)   // 2048 elements per block
#define SCAN_MAXB ((NMAX + SCAN_CHUNK - 1) / SCAN_CHUNK + 1)

// ---------------------------------------------------------------------------
// Scratch (static __device__ globals; runtime alloc is forbidden)
// ---------------------------------------------------------------------------
__device__ __half2 g_h1h[NMAX * 64];  // [N,128] layer-1 features, fp16
__device__ float4  g_out1[NMAX * 32]; // [N,128] layer-1 output (post ELU), fp32
__device__ float4  g_alS1[NMAX];      // [N,4] attention logits (src)
__device__ float4  g_alD1[NMAX];      // [N,4] attention logits (dst)

__device__ __half2 g_h2h[NMAX * 32];  // [N,64] layer-2 features, fp16
__device__ float   g_alS2[NMAX];
__device__ float   g_alD2[NMAX];

__device__ int     g_is64;            // edge_index dtype flag (1 = int64)
__device__ int     g_deg[NMAX];       // dst-degree histogram
__device__ int     g_row[NMAX + 1];   // CSR row offsets (by dst)
__device__ int     g_cursor[NMAX];    // scatter cursors
__device__ int     g_esrc[EMAX];      // src ids sorted by dst
__device__ unsigned long long g_state[SCAN_MAXB];  // lookback: (flag<<32)|value

// ---------------------------------------------------------------------------
// Helpers
// ---------------------------------------------------------------------------
__device__ __forceinline__ float lrelu(float x) {
    return x > 0.f ? x : NEG_SLOPE * x;
}
__device__ __forceinline__ float comp4(float4 v, int i) {
    return i == 0 ? v.x : (i == 1 ? v.y : (i == 2 ? v.z : v.w));
}
__device__ __forceinline__ unsigned f2tf32(float f) {
    unsigned u;
    asm("cvt.rna.tf32.f32 %0, %1;" : "=r"(u) : "f"(f));
    return u;
}
__device__ __forceinline__ void mma_tf32(float c[4],
                                         unsigned a0, unsigned a1,
                                         unsigned a2, unsigned a3,
                                         unsigned b0, unsigned b1) {
    asm volatile(
        "mma.sync.aligned.m16n8k8.row.col.f32.tf32.tf32.f32 "
        "{%0,%1,%2,%3}, {%4,%5,%6,%7}, {%8,%9}, {%0,%1,%2,%3};"
        : "+f"(c[0]), "+f"(c[1]), "+f"(c[2]), "+f"(c[3])
        : "r"(a0), "r"(a1), "r"(a2), "r"(a3), "r"(b0), "r"(b1));
}

// ---------------------------------------------------------------------------
// zero_deg + dtype probe + scan-state reset, fused.
// ---------------------------------------------------------------------------
__global__ void zero_probe_kernel(const void* ei, int n) {
    if (blockIdx.x == 0) {
        __shared__ int bad;
        if (threadIdx.x == 0) bad = 0;
        __syncthreads();
        const long long* p = (const long long*)ei;
        long long v = p[threadIdx.x];
        if (v < 0 || v >= n) atomicOr(&bad, 1);
        __syncthreads();
        if (threadIdx.x == 0) g_is64 = bad ? 0 : 1;
    }
    int i = blockIdx.x * blockDim.x + threadIdx.x;
    if (i < n) g_deg[i] = 0;
    if (i < SCAN_MAXB) g_state[i] = 0ULL;
}

// ---------------------------------------------------------------------------
// CSR build: histogram (4 edges/thread) -> lookback scan -> permute (4/thread)
// ---------------------------------------------------------------------------
__global__ void hist_kernel(const void* __restrict__ ei, int E, int n) {
    int e0 = (blockIdx.x * blockDim.x + threadIdx.x) * 4;
    if (e0 >= E) return;
    int is64 = g_is64;
    int d[4];
#pragma unroll
    for (int i = 0; i < 4; i++) {
        int e = e0 + i;
        int dv = 0;
        if (e < E) {
            if (is64) dv = (int)((const long long*)ei)[E + e];
            else      dv = ((const int*)ei)[E + e];
            dv = min(max(dv, 0), n - 1);
        }
        d[i] = (e < E) ? dv : -1;
    }
#pragma unroll
    for (int i = 0; i < 4; i++)
        if (d[i] >= 0) atomicAdd(&g_deg[d[i]], 1);
}

// Single-kernel exclusive scan with decoupled lookback.
// 25 blocks (all co-resident on 148 SMs -> spin is deadlock-free).
__global__ __launch_bounds__(SCAN_T) void scan_fused_kernel(int n) {
    __shared__ int sm[SCAN_T];
    __shared__ int sprefix;
    int t = threadIdx.x;
    int bid = blockIdx.x;
    int base = bid * SCAN_CHUNK + t * SCAN_I;
    int loc[SCAN_I];
    int s = 0;
#pragma unroll
    for (int i = 0; i < SCAN_I; i++) {
        int idx = base + i;
        loc[i] = (idx < n) ? g_deg[idx] : 0;
        s += loc[i];
    }
    sm[t] = s;
    __syncthreads();
#pragma unroll
    for (int off = 1; off < SCAN_T; off <<= 1) {
        int v = (t >= off) ? sm[t - off] : 0;
        __syncthreads();
        sm[t] += v;
        __syncthreads();
    }
    int total = sm[SCAN_T - 1];

    if (t == 0) {
        atomicExch(&g_state[bid], (1ULL << 32) | (unsigned)total);
        int run = 0;
        for (int i = bid - 1; i >= 0; i--) {
            unsigned long long st;
            do { st = atomicAdd(&g_state[i], 0ULL); } while ((st >> 32) == 0ULL);
            run += (int)(st & 0xFFFFFFFFULL);
            if ((st >> 32) == 2ULL) break;
        }
        atomicExch(&g_state[bid], (2ULL << 32) | (unsigned)(run + total));
        sprefix = run;
    }
    __syncthreads();

    int acc = ((t == 0) ? 0 : sm[t - 1]) + sprefix;
#pragma unroll
    for (int i = 0; i < SCAN_I; i++) {
        int idx = base + i;
        if (idx < n) {
            g_row[idx] = acc;
            g_cursor[idx] = acc;
            acc += loc[i];
        }
    }
    if (bid == gridDim.x - 1 && t == SCAN_T - 1) g_row[n] = sprefix + total;
}

__global__ void permute_kernel(const void* __restrict__ ei, int E, int n) {
    int e0 = (blockIdx.x * blockDim.x + threadIdx.x) * 4;
    if (e0 >= E) return;
    int is64 = g_is64;
    int s[4], d[4];
#pragma unroll
    for (int i = 0; i < 4; i++) {
        int e = e0 + i;
        int sv = 0, dv = -1;
        if (e < E) {
            if (is64) {
                sv = (int)((const long long*)ei)[e];
                dv = (int)((const long long*)ei)[E + e];
            } else {
                sv = ((const int*)ei)[e];
                dv = ((const int*)ei)[E + e];
            }
            sv = min(max(sv, 0), n - 1);
            dv = min(max(dv, 0), n - 1);
        }
        s[i] = sv; d[i] = dv;
    }
    int pos[4];
#pragma unroll
    for (int i = 0; i < 4; i++)
        pos[i] = (d[i] >= 0) ? atomicAdd(&g_cursor[d[i]], 1) : -1;
#pragma unroll
    for (int i = 0; i < 4; i++)
        if (pos[i] >= 0 && pos[i] < EMAX) g_esrc[pos[i]] = s[i];
}

// ---------------------------------------------------------------------------
// TF32 tensor-core GEMM with fused attention-logit epilogue.
// H[M, NC] = X[M, 128] @ W[128, NC] via mma.sync m16n8k8 tf32.
// LAYER 1: NC=128, tile 64x128, warps 4(m) x 2(n).
// LAYER 2: NC=64,  tile 128x64, warps 8(m) x 1(n).
// ---------------------------------------------------------------------------
template <int LAYER>
__global__ __launch_bounds__(256) void gemm_mma_kernel(const float* __restrict__ Xin,
                                                       const float* __restrict__ W,
                                                       const float* __restrict__ aS,
                                                       const float* __restrict__ aD,
                                                       int M) {
    constexpr int NC = (LAYER == 1) ? 128 : 64;
    constexpr int MT = (LAYER == 1) ? 64 : 128;   // rows per block
    constexpr int WM = (LAYER == 1) ? 4 : 8;      // warps along M
    constexpr int XS = 36;                        // Xs row stride
    constexpr int WR = NC + 8;                    // Ws row stride
    const float* __restrict__ X = (LAYER == 1) ? Xin : (const float*)g_out1;
    __half2* __restrict__ Hh = (LAYER == 1) ? g_h1h : g_h2h;

    __shared__ unsigned Xs[MT][XS];   // tf32 bits
    __shared__ unsigned Ws[32][WR];   // tf32 bits

    const int t = threadIdx.x;
    const int w = t >> 5, lane = t & 31;
    const int g = lane >> 2, tig = lane & 3;
    const int wm = w % WM, wn = w / WM;
    const int nb = wn * 64;
    const int row0 = blockIdx.x * MT;

    float c[8][4];
#pragma unroll
    for (int i = 0; i < 8; i++)
#pragma unroll
        for (int j = 0; j < 4; j++) c[i][j] = 0.f;

    for (int kk = 0; kk < 128; kk += 32) {
#pragma unroll
        for (int i = 0; i < MT / 32; i++) {
            int idx = i * 256 + t;
            int r = idx >> 3, c4 = idx & 7;
            int gr = row0 + r;
            float4 v = make_float4(0.f, 0.f, 0.f, 0.f);
            if (gr < M) v = *(const float4*)&X[gr * 128 + kk + c4 * 4];
            unsigned* dst = &Xs[r][c4 * 4];
            dst[0] = f2tf32(v.x); dst[1] = f2tf32(v.y);
            dst[2] = f2tf32(v.z); dst[3] = f2tf32(v.w);
        }
#pragma unroll
        for (int i = 0; i < NC / 32; i++) {
            int idx = i * 256 + t;
            int r = idx / (NC / 4), c4 = idx % (NC / 4);
            float4 v = *(const float4*)&W[(kk + r) * NC + c4 * 4];
            unsigned* dst = &Ws[r][c4 * 4];
            dst[0] = f2tf32(v.x); dst[1] = f2tf32(v.y);
            dst[2] = f2tf32(v.z); dst[3] = f2tf32(v.w);
        }
        __syncthreads();

#pragma unroll
        for (int ks = 0; ks < 4; ks++) {
            int k0 = ks * 8;
            unsigned a0 = Xs[wm * 16 + g][k0 + tig];
            unsigned a1 = Xs[wm * 16 + g + 8][k0 + tig];
            unsigned a2 = Xs[wm * 16 + g][k0 + tig + 4];
            unsigned a3 = Xs[wm * 16 + g + 8][k0 + tig + 4];
#pragma unroll
            for (int nt = 0; nt < 8; nt++) {
                unsigned b0 = Ws[k0 + tig][nb + nt * 8 + g];
                unsigned b1 = Ws[k0 + tig + 4][nb + nt * 8 + g];
                mma_tf32(c[nt], a0, a1, a2, a3, b0, b1);
            }
        }
        __syncthreads();
    }

    const int r0g = row0 + wm * 16 + g;
    const int r1g = r0g + 8;

#pragma unroll
    for (int nt = 0; nt < 8; nt++) {
        int col = nb + nt * 8 + tig * 2;
        if (r0g < M)
            Hh[r0g * (NC / 2) + col / 2] = __floats2half2_rn(c[nt][0], c[nt][1]);
        if (r1g < M)
            Hh[r1g * (NC / 2) + col / 2] = __floats2half2_rn(c[nt][2], c[nt][3]);
    }

    if (LAYER == 1) {
        float sA0[2] = {0.f, 0.f}, sD0[2] = {0.f, 0.f};
        float sA1[2] = {0.f, 0.f}, sD1[2] = {0.f, 0.f};
#pragma unroll
        for (int nt = 0; nt < 8; nt++) {
            int col = nb + nt * 8 + tig * 2;
            int hl = nt >> 2;
            float av0 = aS[col], av1 = aS[col + 1];
            float dv0 = aD[col], dv1 = aD[col + 1];
            sA0[hl] += c[nt][0] * av0 + c[nt][1] * av1;
            sD0[hl] += c[nt][0] * dv0 + c[nt][1] * dv1;
            sA1[hl] += c[nt][2] * av0 + c[nt][3] * av1;
            sD1[hl] += c[nt][2] * dv0 + c[nt][3] * dv1;
        }
#pragma unroll
        for (int off = 1; off <= 2; off <<= 1) {
#pragma unroll
            for (int hl = 0; hl < 2; hl++) {
                sA0[hl] += __shfl_xor_sync(0xFFFFFFFF, sA0[hl], off);
                sD0[hl] += __shfl_xor_sync(0xFFFFFFFF, sD0[hl], off);
                sA1[hl] += __shfl_xor_sync(0xFFFFFFFF, sA1[hl], off);
                sD1[hl] += __shfl_xor_sync(0xFFFFFFFF, sD1[hl], off);
            }
        }
        if (tig == 0) {
            int hb = wn * 2;
            if (r0g < M) {
#pragma unroll
                for (int hl = 0; hl < 2; hl++) {
                    ((float*)g_alS1)[r0g * 4 + hb + hl] = sA0[hl];
                    ((float*)g_alD1)[r0g * 4 + hb + hl] = sD0[hl];
                }
            }
            if (r1g < M) {
#pragma unroll
                for (int hl = 0; hl < 2; hl++) {
                    ((float*)g_alS1)[r1g * 4 + hb + hl] = sA1[hl];
                    ((float*)g_alD1)[r1g * 4 + hb + hl] = sD1[hl];
                }
            }
        }
    } else {
        float sA0 = 0.f, sD0 = 0.f, sA1 = 0.f, sD1 = 0.f;
#pragma unroll
        for (int nt = 0; nt < 8; nt++) {
            int col = nt * 8 + tig * 2;
            float av0 = aS[col], av1 = aS[col + 1];
            float dv0 = aD[col], dv1 = aD[col + 1];
            sA0 += c[nt][0] * av0 + c[nt][1] * av1;
            sD0 += c[nt][0] * dv0 + c[nt][1] * dv1;
            sA1 += c[nt][2] * av0 + c[nt][3] * av1;
            sD1 += c[nt][2] * dv0 + c[nt][3] * dv1;
        }
#pragma unroll
        for (int off = 1; off <= 2; off <<= 1) {
            sA0 += __shfl_xor_sync(0xFFFFFFFF, sA0, off);
            sD0 += __shfl_xor_sync(0xFFFFFFFF, sD0, off);
            sA1 += __shfl_xor_sync(0xFFFFFFFF, sA1, off);
            sD1 += __shfl_xor_sync(0xFFFFFFFF, sD1, off);
        }
        if (tig == 0) {
            if (r0g < M) { g_alS2[r0g] = sA0; g_alD2[r0g] = sD0; }
            if (r1g < M) { g_alS2[r1g] = sA1; g_alD2[r1g] = sD1; }
        }
    }
}

// ---------------------------------------------------------------------------
// Fused GAT layer 1 (proven version): warp per dst node, 8B/lane fp16 gather,
// register accumulation, self-loop folded, ELU. No atomics.
// ---------------------------------------------------------------------------
__global__ __launch_bounds__(256) void gat1_kernel(const float* __restrict__ b1,
                                                   int n) {
    __shared__ int ssrc[8][32];
    __shared__ float4 sev[8][32];

    int w = threadIdx.x >> 5;
    int lane = threadIdx.x & 31;
    int node = blockIdx.x * 8 + w;
    if (node >= n) return;
    int head = lane >> 3;

    int r0 = g_row[node];
    int r1 = g_row[node + 1];
    float4 ad = g_alD1[node];

    float4 accv = make_float4(0.f, 0.f, 0.f, 0.f);
    float4 den = make_float4(0.f, 0.f, 0.f, 0.f);

    for (int base = r0; base < r1; base += 32) {
        int e = base + lane;
        int s = 0;
        float4 ev = make_float4(0.f, 0.f, 0.f, 0.f);
        if (e < r1) {
            s = g_esrc[e];
            float4 as = g_alS1[s];
            ev.x = __expf(lrelu(as.x + ad.x));
            ev.y = __expf(lrelu(as.y + ad.y));
            ev.z = __expf(lrelu(as.z + ad.z));
            ev.w = __expf(lrelu(as.w + ad.w));
            den.x += ev.x; den.y += ev.y; den.z += ev.z; den.w += ev.w;
        }
        ssrc[w][lane] = s;
        sev[w][lane] = ev;
        __syncwarp();

        int cnt = min(32, r1 - base);
#pragma unroll 4
        for (int j = 0; j < cnt; j++) {
            int sj = ssrc[w][j];                           // smem broadcast
            float sc = ((const float*)(sev[w] + j))[head]; // conflict-free
            uint2 raw = *reinterpret_cast<const uint2*>(&g_h1h[sj * 64 + lane * 2]);
            float2 va = __half22float2(*reinterpret_cast<__half2*>(&raw.x));
            float2 vb = __half22float2(*reinterpret_cast<__half2*>(&raw.y));
            accv.x += va.x * sc;
            accv.y += va.y * sc;
            accv.z += vb.x * sc;
            accv.w += vb.y * sc;
        }
        __syncwarp();
    }

#pragma unroll
    for (int off = 16; off > 0; off >>= 1) {
        den.x += __shfl_xor_sync(0xFFFFFFFF, den.x, off);
        den.y += __shfl_xor_sync(0xFFFFFFFF, den.y, off);
        den.z += __shfl_xor_sync(0xFFFFFFFF, den.z, off);
        den.w += __shfl_xor_sync(0xFFFFFFFF, den.w, off);
    }

    float4 asn = g_alS1[node];
    float4 evs;
    evs.x = __expf(lrelu(asn.x + ad.x));
    evs.y = __expf(lrelu(asn.y + ad.y));
    evs.z = __expf(lrelu(asn.z + ad.z));
    evs.w = __expf(lrelu(asn.w + ad.w));
    float eh = comp4(evs, head);
    {
        uint2 raw = *reinterpret_cast<const uint2*>(&g_h1h[node * 64 + lane * 2]);
        float2 va = __half22float2(*reinterpret_cast<__half2*>(&raw.x));
        float2 vb = __half22float2(*reinterpret_cast<__half2*>(&raw.y));
        accv.x += eh * va.x;
        accv.y += eh * va.y;
        accv.z += eh * vb.x;
        accv.w += eh * vb.y;
    }

    float inv = 1.f / (comp4(den, head) + eh + 1e-16f);
    float4 bv = ((const float4*)b1)[lane];
    float4 o;
    o.x = accv.x * inv + bv.x;
    o.y = accv.y * inv + bv.y;
    o.z = accv.z * inv + bv.z;
    o.w = accv.w * inv + bv.w;
    o.x = o.x > 0.f ? o.x : expm1f(o.x);
    o.y = o.y > 0.f ? o.y : expm1f(o.y);
    o.z = o.z > 0.f ? o.z : expm1f(o.z);
    o.w = o.w > 0.f ? o.w : expm1f(o.w);
    g_out1[node * 32 + lane] = o;
}

// ---------------------------------------------------------------------------
// Fused GAT layer 2 (proven version): warp per dst node, 1 head, 64 ch fp16.
// ---------------------------------------------------------------------------
__global__ __launch_bounds__(256) void gat2_kernel(const float* __restrict__ b2,
                                                   float* __restrict__ out,
                                                   int n) {
    __shared__ int ssrc[8][32];
    __shared__ float sev[8][32];

    int w = threadIdx.x >> 5;
    int lane = threadIdx.x & 31;
    int node = blockIdx.x * 8 + w;
    if (node >= n) return;

    int r0 = g_row[node];
    int r1 = g_row[node + 1];
    float ad = g_alD2[node];

    float2 accv = make_float2(0.f, 0.f);
    float den = 0.f;

    for (int base = r0; base < r1; base += 32) {
        int e = base + lane;
        int s = 0;
        float ev = 0.f;
        if (e < r1) {
            s = g_esrc[e];
            ev = __expf(lrelu(g_alS2[s] + ad));
            den += ev;
        }
        ssrc[w][lane] = s;
        sev[w][lane] = ev;
        __syncwarp();

        int cnt = min(32, r1 - base);
#pragma unroll 4
        for (int j = 0; j < cnt; j++) {
            int sj = ssrc[w][j];
            float ee = sev[w][j];
            float2 v = __half22float2(g_h2h[sj * 32 + lane]);
            accv.x += v.x * ee;
            accv.y += v.y * ee;
        }
        __syncwarp();
    }

#pragma unroll
    for (int off = 16; off > 0; off >>= 1)
        den += __shfl_xor_sync(0xFFFFFFFF, den, off);

    float eh = __expf(lrelu(g_alS2[node] + ad));
    float2 hv = __half22float2(g_h2h[node * 32 + lane]);
    accv.x += eh * hv.x;
    accv.y += eh * hv.y;

    float inv = 1.f / (den + eh + 1e-16f);
    float2 bv = ((const float2*)b2)[lane];
    float2 o;
    o.x = accv.x * inv + bv.x;
    o.y = accv.y * inv + bv.y;
    ((float2*)out)[node * 32 + lane] = o;
}

// ---------------------------------------------------------------------------
// Launch: CSR build forked onto a side stream, overlapped with gemm1.
// ---------------------------------------------------------------------------
extern "C" void kernel_launch(void* const* d_in, const int* in_sizes, int n_in,
                              void* d_out, int out_size) {
    const float* x   = (const float*)d_in[0];
    const void*  ei  = d_in[1];
    const float* W1  = (const float*)d_in[2];
    const float* aS1 = (const float*)d_in[3];
    const float* aD1 = (const float*)d_in[4];
    const float* b1  = (const float*)d_in[5];
    const float* W2  = (const float*)d_in[6];
    const float* aS2 = (const float*)d_in[7];
    const float* aD2 = (const float*)d_in[8];
    const float* b2  = (const float*)d_in[9];
    float* out       = (float*)d_out;

    const int n = in_sizes[0] / 128;
    const int E = in_sizes[1] / 2;

    const int gemm1_blocks = (n + 63) / 64;
    const int gemm2_blocks = (n + 127) / 128;
    const int node_blocks = (n + 7) / 8;          // warp per node
    const int edge4_blocks = (E + 1023) / 1024;   // 4 edges per thread
    const int scan_blocks = (n + SCAN_CHUNK - 1) / SCAN_CHUNK;

    cudaStream_t side = nullptr;
    cudaEvent_t evF = nullptr, evJ = nullptr;
    bool fork = (cudaStreamCreateWithFlags(&side, cudaStreamNonBlocking) == cudaSuccess);
    if (fork) fork = (cudaEventCreateWithFlags(&evF, cudaEventDisableTiming) == cudaSuccess);
    if (fork) fork = (cudaEventCreateWithFlags(&evJ, cudaEventDisableTiming) == cudaSuccess);

    if (fork) {
        cudaEventRecord(evF, 0);
        cudaStreamWaitEvent(side, evF, 0);
        zero_probe_kernel<<<(n + 255) / 256, 256, 0, side>>>(ei, n);
        hist_kernel<<<edge4_blocks, 256, 0, side>>>(ei, E, n);
        scan_fused_kernel<<<scan_blocks, SCAN_T, 0, side>>>(n);
        permute_kernel<<<edge4_blocks, 256, 0, side>>>(ei, E, n);
        cudaEventRecord(evJ, side);

        gemm_mma_kernel<1><<<gemm1_blocks, 256>>>(x, W1, aS1, aD1, n);

        cudaStreamWaitEvent(0, evJ, 0);
    } else {
        zero_probe_kernel<<<(n + 255) / 256, 256>>>(ei, n);
        hist_kernel<<<edge4_blocks, 256>>>(ei, E, n);
        scan_fused_kernel<<<scan_blocks, SCAN_T>>>(n);
        permute_kernel<<<edge4_blocks, 256>>>(ei, E, n);
        gemm_mma_kernel<1><<<gemm1_blocks, 256>>>(x, W1, aS1, aD1, n);
    }

    gat1_kernel<<<node_blocks, 256>>>(b1, n);
    gemm_mma_kernel<2><<<gemm2_blocks, 256>>>(nullptr, W2, aS2, aD2, n);
    gat2_kernel<<<node_blocks, 256>>>(b2, out, n);

    if (evF) cudaEventDestroy(evF);
    if (evJ) cudaEventDestroy(evJ);
    if (side) cudaStreamDestroy(side);
}

// round 17
// speedup vs baseline: 1.0826x; 1.0040x over previous
#include <cuda_runtime.h>
#include <cuda_fp16.h>
#include <math.h>

// Problem constants (fixed by the reference)
#define NMAX 50000
#define EMAX 1600000
#define NEG_SLOPE 0.2f

#define SCAN_T 256
#define SCAN_I 8
#define SCAN_CHUNK (SCAN_T * SCAN_I)   // 2048 elements per block
// scan now runs over 4*N quarter-split counters
#define SCAN_MAXB ((4 * NMAX + SCAN_CHUNK - 1) / SCAN_CHUNK + 1)

// ---------------------------------------------------------------------------
// Scratch (static __device__ globals; runtime alloc is forbidden)
// ---------------------------------------------------------------------------
__device__ __half2 g_h1h[NMAX * 64];  // [N,128] layer-1 features, fp16
__device__ float4  g_out1[NMAX * 32]; // [N,128] layer-1 output (post ELU), fp32
__device__ float4  g_alS1[NMAX];      // [N,4] attention logits (src)
__device__ float4  g_alD1[NMAX];      // [N,4] attention logits (dst)

__device__ __half2 g_h2h[NMAX * 32];  // [N,64] layer-2 features, fp16
__device__ float   g_alS2[NMAX];
__device__ float   g_alD2[NMAX];

__device__ int     g_is64;              // edge_index dtype flag (1 = int64)
__device__ int     g_deg4[NMAX * 4];    // quarter-split histogram [d*4+q]
__device__ int     g_row[NMAX + 1];     // CSR row offsets (by dst)
__device__ int     g_cursor4[NMAX * 4]; // quarter-split scatter cursors
__device__ int     g_esrc[EMAX];        // src ids sorted by dst
__device__ unsigned long long g_state[SCAN_MAXB];  // lookback: (flag<<32)|value

// ---------------------------------------------------------------------------
// Helpers
// ---------------------------------------------------------------------------
__device__ __forceinline__ float lrelu(float x) {
    return x > 0.f ? x : NEG_SLOPE * x;
}
__device__ __forceinline__ float comp4(float4 v, int i) {
    return i == 0 ? v.x : (i == 1 ? v.y : (i == 2 ? v.z : v.w));
}
__device__ __forceinline__ unsigned f2tf32(float f) {
    unsigned u;
    asm("cvt.rna.tf32.f32 %0, %1;" : "=r"(u) : "f"(f));
    return u;
}
__device__ __forceinline__ void mma_tf32(float c[4],
                                         unsigned a0, unsigned a1,
                                         unsigned a2, unsigned a3,
                                         unsigned b0, unsigned b1) {
    asm volatile(
        "mma.sync.aligned.m16n8k8.row.col.f32.tf32.tf32.f32 "
        "{%0,%1,%2,%3}, {%4,%5,%6,%7}, {%8,%9}, {%0,%1,%2,%3};"
        : "+f"(c[0]), "+f"(c[1]), "+f"(c[2]), "+f"(c[3])
        : "r"(a0), "r"(a1), "r"(a2), "r"(a3), "r"(b0), "r"(b1));
}

// ---------------------------------------------------------------------------
// zero_deg4 + dtype probe + scan-state reset, fused. Grid covers 4n.
// ---------------------------------------------------------------------------
__global__ void zero_probe_kernel(const void* ei, int n) {
    if (blockIdx.x == 0) {
        __shared__ int bad;
        if (threadIdx.x == 0) bad = 0;
        __syncthreads();
        const long long* p = (const long long*)ei;
        long long v = p[threadIdx.x];
        if (v < 0 || v >= n) atomicOr(&bad, 1);
        __syncthreads();
        if (threadIdx.x == 0) g_is64 = bad ? 0 : 1;
    }
    int i = blockIdx.x * blockDim.x + threadIdx.x;
    if (i < 4 * n) g_deg4[i] = 0;
    if (i < SCAN_MAXB) g_state[i] = 0ULL;
}

// ---------------------------------------------------------------------------
// CSR build with quarter-split counters (q = e & 3): per-address atomic
// contention drops 4x (32 -> ~8 ops/address).
// ---------------------------------------------------------------------------
__global__ void hist_kernel(const void* __restrict__ ei, int E, int n) {
    int e0 = (blockIdx.x * blockDim.x + threadIdx.x) * 4;
    if (e0 >= E) return;
    int is64 = g_is64;
    int d[4];
#pragma unroll
    for (int i = 0; i < 4; i++) {
        int e = e0 + i;
        int dv = -1;
        if (e < E) {
            if (is64) dv = (int)((const long long*)ei)[E + e];
            else      dv = ((const int*)ei)[E + e];
            dv = min(max(dv, 0), n - 1);
        }
        d[i] = dv;
    }
#pragma unroll
    for (int i = 0; i < 4; i++)
        if (d[i] >= 0) atomicAdd(&g_deg4[d[i] * 4 + ((e0 + i) & 3)], 1);
}

// Single-kernel exclusive scan with decoupled lookback over m = 4n counters
// (node-major, quarter-minor). 98 blocks co-resident on 148 SMs.
__global__ __launch_bounds__(SCAN_T) void scan_fused_kernel(int n) {
    __shared__ int sm[SCAN_T];
    __shared__ int sprefix;
    const int m = 4 * n;
    int t = threadIdx.x;
    int bid = blockIdx.x;
    int base = bid * SCAN_CHUNK + t * SCAN_I;
    int loc[SCAN_I];
    int s = 0;
#pragma unroll
    for (int i = 0; i < SCAN_I; i++) {
        int idx = base + i;
        loc[i] = (idx < m) ? g_deg4[idx] : 0;
        s += loc[i];
    }
    sm[t] = s;
    __syncthreads();
#pragma unroll
    for (int off = 1; off < SCAN_T; off <<= 1) {
        int v = (t >= off) ? sm[t - off] : 0;
        __syncthreads();
        sm[t] += v;
        __syncthreads();
    }
    int total = sm[SCAN_T - 1];

    if (t == 0) {
        atomicExch(&g_state[bid], (1ULL << 32) | (unsigned)total);
        int run = 0;
        for (int i = bid - 1; i >= 0; i--) {
            unsigned long long st;
            do { st = atomicAdd(&g_state[i], 0ULL); } while ((st >> 32) == 0ULL);
            run += (int)(st & 0xFFFFFFFFULL);
            if ((st >> 32) == 2ULL) break;
        }
        atomicExch(&g_state[bid], (2ULL << 32) | (unsigned)(run + total));
        sprefix = run;
    }
    __syncthreads();

    int acc = ((t == 0) ? 0 : sm[t - 1]) + sprefix;
#pragma unroll
    for (int i = 0; i < SCAN_I; i++) {
        int idx = base + i;
        if (idx < m) {
            g_cursor4[idx] = acc;
            if ((idx & 3) == 0) g_row[idx >> 2] = acc;  // row[d] = prefix at (d,0)
            acc += loc[i];
        }
    }
    if (bid == gridDim.x - 1 && t == SCAN_T - 1) g_row[n] = sprefix + total;
}

__global__ void permute_kernel(const void* __restrict__ ei, int E, int n) {
    int e0 = (blockIdx.x * blockDim.x + threadIdx.x) * 4;
    if (e0 >= E) return;
    int is64 = g_is64;
    int s[4], d[4];
#pragma unroll
    for (int i = 0; i < 4; i++) {
        int e = e0 + i;
        int sv = 0, dv = -1;
        if (e < E) {
            if (is64) {
                sv = (int)((const long long*)ei)[e];
                dv = (int)((const long long*)ei)[E + e];
            } else {
                sv = ((const int*)ei)[e];
                dv = ((const int*)ei)[E + e];
            }
            sv = min(max(sv, 0), n - 1);
            dv = min(max(dv, 0), n - 1);
        }
        s[i] = sv; d[i] = dv;
    }
    int pos[4];
#pragma unroll
    for (int i = 0; i < 4; i++)
        pos[i] = (d[i] >= 0)
                 ? atomicAdd(&g_cursor4[d[i] * 4 + ((e0 + i) & 3)], 1) : -1;
#pragma unroll
    for (int i = 0; i < 4; i++)
        if (pos[i] >= 0 && pos[i] < EMAX) g_esrc[pos[i]] = s[i];
}

// ---------------------------------------------------------------------------
// TF32 tensor-core GEMM with fused attention-logit epilogue.
// H[M, NC] = X[M, 128] @ W[128, NC] via mma.sync m16n8k8 tf32.
// LAYER 1: NC=128, tile 64x128, warps 4(m) x 2(n).
// LAYER 2: NC=64,  tile 128x64, warps 8(m) x 1(n).
// ---------------------------------------------------------------------------
template <int LAYER>
__global__ __launch_bounds__(256) void gemm_mma_kernel(const float* __restrict__ Xin,
                                                       const float* __restrict__ W,
                                                       const float* __restrict__ aS,
                                                       const float* __restrict__ aD,
                                                       int M) {
    constexpr int NC = (LAYER == 1) ? 128 : 64;
    constexpr int MT = (LAYER == 1) ? 64 : 128;   // rows per block
    constexpr int WM = (LAYER == 1) ? 4 : 8;      // warps along M
    constexpr int XS = 36;                        // Xs row stride
    constexpr int WR = NC + 8;                    // Ws row stride
    const float* __restrict__ X = (LAYER == 1) ? Xin : (const float*)g_out1;
    __half2* __restrict__ Hh = (LAYER == 1) ? g_h1h : g_h2h;

    __shared__ unsigned Xs[MT][XS];   // tf32 bits
    __shared__ unsigned Ws[32][WR];   // tf32 bits

    const int t = threadIdx.x;
    const int w = t >> 5, lane = t & 31;
    const int g = lane >> 2, tig = lane & 3;
    const int wm = w % WM, wn = w / WM;
    const int nb = wn * 64;
    const int row0 = blockIdx.x * MT;

    float c[8][4];
#pragma unroll
    for (int i = 0; i < 8; i++)
#pragma unroll
        for (int j = 0; j < 4; j++) c[i][j] = 0.f;

    for (int kk = 0; kk < 128; kk += 32) {
#pragma unroll
        for (int i = 0; i < MT / 32; i++) {
            int idx = i * 256 + t;
            int r = idx >> 3, c4 = idx & 7;
            int gr = row0 + r;
            float4 v = make_float4(0.f, 0.f, 0.f, 0.f);
            if (gr < M) v = *(const float4*)&X[gr * 128 + kk + c4 * 4];
            unsigned* dst = &Xs[r][c4 * 4];
            dst[0] = f2tf32(v.x); dst[1] = f2tf32(v.y);
            dst[2] = f2tf32(v.z); dst[3] = f2tf32(v.w);
        }
#pragma unroll
        for (int i = 0; i < NC / 32; i++) {
            int idx = i * 256 + t;
            int r = idx / (NC / 4), c4 = idx % (NC / 4);
            float4 v = *(const float4*)&W[(kk + r) * NC + c4 * 4];
            unsigned* dst = &Ws[r][c4 * 4];
            dst[0] = f2tf32(v.x); dst[1] = f2tf32(v.y);
            dst[2] = f2tf32(v.z); dst[3] = f2tf32(v.w);
        }
        __syncthreads();

#pragma unroll
        for (int ks = 0; ks < 4; ks++) {
            int k0 = ks * 8;
            unsigned a0 = Xs[wm * 16 + g][k0 + tig];
            unsigned a1 = Xs[wm * 16 + g + 8][k0 + tig];
            unsigned a2 = Xs[wm * 16 + g][k0 + tig + 4];
            unsigned a3 = Xs[wm * 16 + g + 8][k0 + tig + 4];
#pragma unroll
            for (int nt = 0; nt < 8; nt++) {
                unsigned b0 = Ws[k0 + tig][nb + nt * 8 + g];
                unsigned b1 = Ws[k0 + tig + 4][nb + nt * 8 + g];
                mma_tf32(c[nt], a0, a1, a2, a3, b0, b1);
            }
        }
        __syncthreads();
    }

    const int r0g = row0 + wm * 16 + g;
    const int r1g = r0g + 8;

#pragma unroll
    for (int nt = 0; nt < 8; nt++) {
        int col = nb + nt * 8 + tig * 2;
        if (r0g < M)
            Hh[r0g * (NC / 2) + col / 2] = __floats2half2_rn(c[nt][0], c[nt][1]);
        if (r1g < M)
            Hh[r1g * (NC / 2) + col / 2] = __floats2half2_rn(c[nt][2], c[nt][3]);
    }

    if (LAYER == 1) {
        float sA0[2] = {0.f, 0.f}, sD0[2] = {0.f, 0.f};
        float sA1[2] = {0.f, 0.f}, sD1[2] = {0.f, 0.f};
#pragma unroll
        for (int nt = 0; nt < 8; nt++) {
            int col = nb + nt * 8 + tig * 2;
            int hl = nt >> 2;
            float av0 = aS[col], av1 = aS[col + 1];
            float dv0 = aD[col], dv1 = aD[col + 1];
            sA0[hl] += c[nt][0] * av0 + c[nt][1] * av1;
            sD0[hl] += c[nt][0] * dv0 + c[nt][1] * dv1;
            sA1[hl] += c[nt][2] * av0 + c[nt][3] * av1;
            sD1[hl] += c[nt][2] * dv0 + c[nt][3] * dv1;
        }
#pragma unroll
        for (int off = 1; off <= 2; off <<= 1) {
#pragma unroll
            for (int hl = 0; hl < 2; hl++) {
                sA0[hl] += __shfl_xor_sync(0xFFFFFFFF, sA0[hl], off);
                sD0[hl] += __shfl_xor_sync(0xFFFFFFFF, sD0[hl], off);
                sA1[hl] += __shfl_xor_sync(0xFFFFFFFF, sA1[hl], off);
                sD1[hl] += __shfl_xor_sync(0xFFFFFFFF, sD1[hl], off);
            }
        }
        if (tig == 0) {
            int hb = wn * 2;
            if (r0g < M) {
#pragma unroll
                for (int hl = 0; hl < 2; hl++) {
                    ((float*)g_alS1)[r0g * 4 + hb + hl] = sA0[hl];
                    ((float*)g_alD1)[r0g * 4 + hb + hl] = sD0[hl];
                }
            }
            if (r1g < M) {
#pragma unroll
                for (int hl = 0; hl < 2; hl++) {
                    ((float*)g_alS1)[r1g * 4 + hb + hl] = sA1[hl];
                    ((float*)g_alD1)[r1g * 4 + hb + hl] = sD1[hl];
                }
            }
        }
    } else {
        float sA0 = 0.f, sD0 = 0.f, sA1 = 0.f, sD1 = 0.f;
#pragma unroll
        for (int nt = 0; nt < 8; nt++) {
            int col = nt * 8 + tig * 2;
            float av0 = aS[col], av1 = aS[col + 1];
            float dv0 = aD[col], dv1 = aD[col + 1];
            sA0 += c[nt][0] * av0 + c[nt][1] * av1;
            sD0 += c[nt][0] * dv0 + c[nt][1] * dv1;
            sA1 += c[nt][2] * av0 + c[nt][3] * av1;
            sD1 += c[nt][2] * dv0 + c[nt][3] * dv1;
        }
#pragma unroll
        for (int off = 1; off <= 2; off <<= 1) {
            sA0 += __shfl_xor_sync(0xFFFFFFFF, sA0, off);
            sD0 += __shfl_xor_sync(0xFFFFFFFF, sD0, off);
            sA1 += __shfl_xor_sync(0xFFFFFFFF, sA1, off);
            sD1 += __shfl_xor_sync(0xFFFFFFFF, sD1, off);
        }
        if (tig == 0) {
            if (r0g < M) { g_alS2[r0g] = sA0; g_alD2[r0g] = sD0; }
            if (r1g < M) { g_alS2[r1g] = sA1; g_alD2[r1g] = sD1; }
        }
    }
}

// ---------------------------------------------------------------------------
// Fused GAT layer 1 (proven version): warp per dst node, 8B/lane fp16 gather,
// register accumulation, self-loop folded, ELU. No atomics.
// ---------------------------------------------------------------------------
__global__ __launch_bounds__(256) void gat1_kernel(const float* __restrict__ b1,
                                                   int n) {
    __shared__ int ssrc[8][32];
    __shared__ float4 sev[8][32];

    int w = threadIdx.x >> 5;
    int lane = threadIdx.x & 31;
    int node = blockIdx.x * 8 + w;
    if (node >= n) return;
    int head = lane >> 3;

    int r0 = g_row[node];
    int r1 = g_row[node + 1];
    float4 ad = g_alD1[node];

    float4 accv = make_float4(0.f, 0.f, 0.f, 0.f);
    float4 den = make_float4(0.f, 0.f, 0.f, 0.f);

    for (int base = r0; base < r1; base += 32) {
        int e = base + lane;
        int s = 0;
        float4 ev = make_float4(0.f, 0.f, 0.f, 0.f);
        if (e < r1) {
            s = g_esrc[e];
            float4 as = g_alS1[s];
            ev.x = __expf(lrelu(as.x + ad.x));
            ev.y = __expf(lrelu(as.y + ad.y));
            ev.z = __expf(lrelu(as.z + ad.z));
            ev.w = __expf(lrelu(as.w + ad.w));
            den.x += ev.x; den.y += ev.y; den.z += ev.z; den.w += ev.w;
        }
        ssrc[w][lane] = s;
        sev[w][lane] = ev;
        __syncwarp();

        int cnt = min(32, r1 - base);
#pragma unroll 4
        for (int j = 0; j < cnt; j++) {
            int sj = ssrc[w][j];                           // smem broadcast
            float sc = ((const float*)(sev[w] + j))[head]; // conflict-free
            uint2 raw = *reinterpret_cast<const uint2*>(&g_h1h[sj * 64 + lane * 2]);
            float2 va = __half22float2(*reinterpret_cast<__half2*>(&raw.x));
            float2 vb = __half22float2(*reinterpret_cast<__half2*>(&raw.y));
            accv.x += va.x * sc;
            accv.y += va.y * sc;
            accv.z += vb.x * sc;
            accv.w += vb.y * sc;
        }
        __syncwarp();
    }

#pragma unroll
    for (int off = 16; off > 0; off >>= 1) {
        den.x += __shfl_xor_sync(0xFFFFFFFF, den.x, off);
        den.y += __shfl_xor_sync(0xFFFFFFFF, den.y, off);
        den.z += __shfl_xor_sync(0xFFFFFFFF, den.z, off);
        den.w += __shfl_xor_sync(0xFFFFFFFF, den.w, off);
    }

    float4 asn = g_alS1[node];
    float4 evs;
    evs.x = __expf(lrelu(asn.x + ad.x));
    evs.y = __expf(lrelu(asn.y + ad.y));
    evs.z = __expf(lrelu(asn.z + ad.z));
    evs.w = __expf(lrelu(asn.w + ad.w));
    float eh = comp4(evs, head);
    {
        uint2 raw = *reinterpret_cast<const uint2*>(&g_h1h[node * 64 + lane * 2]);
        float2 va = __half22float2(*reinterpret_cast<__half2*>(&raw.x));
        float2 vb = __half22float2(*reinterpret_cast<__half2*>(&raw.y));
        accv.x += eh * va.x;
        accv.y += eh * va.y;
        accv.z += eh * vb.x;
        accv.w += eh * vb.y;
    }

    float inv = 1.f / (comp4(den, head) + eh + 1e-16f);
    float4 bv = ((const float4*)b1)[lane];
    float4 o;
    o.x = accv.x * inv + bv.x;
    o.y = accv.y * inv + bv.y;
    o.z = accv.z * inv + bv.z;
    o.w = accv.w * inv + bv.w;
    o.x = o.x > 0.f ? o.x : expm1f(o.x);
    o.y = o.y > 0.f ? o.y : expm1f(o.y);
    o.z = o.z > 0.f ? o.z : expm1f(o.z);
    o.w = o.w > 0.f ? o.w : expm1f(o.w);
    g_out1[node * 32 + lane] = o;
}

// ---------------------------------------------------------------------------
// Fused GAT layer 2 (proven version): warp per dst node, 1 head, 64 ch fp16.
// ---------------------------------------------------------------------------
__global__ __launch_bounds__(256) void gat2_kernel(const float* __restrict__ b2,
                                                   float* __restrict__ out,
                                                   int n) {
    __shared__ int ssrc[8][32];
    __shared__ float sev[8][32];

    int w = threadIdx.x >> 5;
    int lane = threadIdx.x & 31;
    int node = blockIdx.x * 8 + w;
    if (node >= n) return;

    int r0 = g_row[node];
    int r1 = g_row[node + 1];
    float ad = g_alD2[node];

    float2 accv = make_float2(0.f, 0.f);
    float den = 0.f;

    for (int base = r0; base < r1; base += 32) {
        int e = base + lane;
        int s = 0;
        float ev = 0.f;
        if (e < r1) {
            s = g_esrc[e];
            ev = __expf(lrelu(g_alS2[s] + ad));
            den += ev;
        }
        ssrc[w][lane] = s;
        sev[w][lane] = ev;
        __syncwarp();

        int cnt = min(32, r1 - base);
#pragma unroll 4
        for (int j = 0; j < cnt; j++) {
            int sj = ssrc[w][j];
            float ee = sev[w][j];
            float2 v = __half22float2(g_h2h[sj * 32 + lane]);
            accv.x += v.x * ee;
            accv.y += v.y * ee;
        }
        __syncwarp();
    }

#pragma unroll
    for (int off = 16; off > 0; off >>= 1)
        den += __shfl_xor_sync(0xFFFFFFFF, den, off);

    float eh = __expf(lrelu(g_alS2[node] + ad));
    float2 hv = __half22float2(g_h2h[node * 32 + lane]);
    accv.x += eh * hv.x;
    accv.y += eh * hv.y;

    float inv = 1.f / (den + eh + 1e-16f);
    float2 bv = ((const float2*)b2)[lane];
    float2 o;
    o.x = accv.x * inv + bv.x;
    o.y = accv.y * inv + bv.y;
    ((float2*)out)[node * 32 + lane] = o;
}

// ---------------------------------------------------------------------------
// Launch: CSR build forked onto a side stream, overlapped with gemm1.
// ---------------------------------------------------------------------------
extern "C" void kernel_launch(void* const* d_in, const int* in_sizes, int n_in,
                              void* d_out, int out_size) {
    const float* x   = (const float*)d_in[0];
    const void*  ei  = d_in[1];
    const float* W1  = (const float*)d_in[2];
    const float* aS1 = (const float*)d_in[3];
    const float* aD1 = (const float*)d_in[4];
    const float* b1  = (const float*)d_in[5];
    const float* W2  = (const float*)d_in[6];
    const float* aS2 = (const float*)d_in[7];
    const float* aD2 = (const float*)d_in[8];
    const float* b2  = (const float*)d_in[9];
    float* out       = (float*)d_out;

    const int n = in_sizes[0] / 128;
    const int E = in_sizes[1] / 2;

    const int gemm1_blocks = (n + 63) / 64;
    const int gemm2_blocks = (n + 127) / 128;
    const int node_blocks = (n + 7) / 8;          // warp per node
    const int edge4_blocks = (E + 1023) / 1024;   // 4 edges per thread
    const int zero_blocks = (4 * n + 255) / 256;
    const int scan_blocks = (4 * n + SCAN_CHUNK - 1) / SCAN_CHUNK;

    cudaStream_t side = nullptr;
    cudaEvent_t evF = nullptr, evJ = nullptr;
    bool fork = (cudaStreamCreateWithFlags(&side, cudaStreamNonBlocking) == cudaSuccess);
    if (fork) fork = (cudaEventCreateWithFlags(&evF, cudaEventDisableTiming) == cudaSuccess);
    if (fork) fork = (cudaEventCreateWithFlags(&evJ, cudaEventDisableTiming) == cudaSuccess);

    if (fork) {
        cudaEventRecord(evF, 0);
        cudaStreamWaitEvent(side, evF, 0);
        zero_probe_kernel<<<zero_blocks, 256, 0, side>>>(ei, n);
        hist_kernel<<<edge4_blocks, 256, 0, side>>>(ei, E, n);
        scan_fused_kernel<<<scan_blocks, SCAN_T, 0, side>>>(n);
        permute_kernel<<<edge4_blocks, 256, 0, side>>>(ei, E, n);
        cudaEventRecord(evJ, side);

        gemm_mma_kernel<1><<<gemm1_blocks, 256>>>(x, W1, aS1, aD1, n);

        cudaStreamWaitEvent(0, evJ, 0);
    } else {
        zero_probe_kernel<<<zero_blocks, 256>>>(ei, n);
        hist_kernel<<<edge4_blocks, 256>>>(ei, E, n);
        scan_fused_kernel<<<scan_blocks, SCAN_T>>>(n);
        permute_kernel<<<edge4_blocks, 256>>>(ei, E, n);
        gemm_mma_kernel<1><<<gemm1_blocks, 256>>>(x, W1, aS1, aD1, n);
    }

    gat1_kernel<<<node_blocks, 256>>>(b1, n);
    gemm_mma_kernel<2><<<gemm2_blocks, 256>>>(nullptr, W2, aS2, aD2, n);
    gat2_kernel<<<node_blocks, 256>>>(b2, out, n);

    if (evF) cudaEventDestroy(evF);
    if (evJ) cudaEventDestroy(evJ);
    if (side) cudaStreamDestroy(side);
}